// round 3
// baseline (speedup 1.0000x reference)
#include <cuda_runtime.h>

#define NUM_USERS 100000
#define N_NODES   150000
#define D         64
#define EDGES     2000000
#define BATCH     1024

// ---------------- scratch (device globals: allocation-free) ----------------
__device__ float g_x0[(size_t)N_NODES * D];   // 38.4 MB
__device__ float g_x1[(size_t)N_NODES * D];   // 38.4 MB
__device__ float g_norm[EDGES];               // 8 MB
__device__ float g_deg[N_NODES];
__device__ float g_cnt[N_NODES];
__device__ float g_usum[D];
__device__ float g_acc[D];
__device__ float g_z[1];

// ---------------- degree histogram over row ----------------
__global__ void deg_k(const int* __restrict__ row) {
    int t = blockIdx.x * blockDim.x + threadIdx.x;
    if (t < EDGES) atomicAdd(&g_deg[row[t]], 1.0f);
}

// ---------------- per-edge symmetric normalization ----------------
__global__ void norm_k(const int* __restrict__ row, const int* __restrict__ col) {
    int t = blockIdx.x * blockDim.x + threadIdx.x;
    if (t < EDGES) {
        float dr = g_deg[row[t]];
        float dc = g_deg[col[t]];
        g_norm[t] = rsqrtf(fmaxf(dr, 1.0f)) * rsqrtf(fmaxf(dc, 1.0f));
    }
}

// ---------------- one propagation layer: xout[col] += norm * xin[row] ------
// 16 threads per edge, each moving one float4 (256B per edge vector).
__global__ void __launch_bounds__(256) prop_k(const float4* __restrict__ xin,
                                              float* __restrict__ xout,
                                              const int* __restrict__ row,
                                              const int* __restrict__ col) {
    unsigned t = blockIdx.x * blockDim.x + threadIdx.x;   // < 32e6
    unsigned e = t >> 4;
    unsigned l = t & 15;
    if (e >= EDGES) return;
    int r = row[e];
    int c = col[e];
    float nv = g_norm[e];
    float4 v = xin[(size_t)r * 16 + l];
    v.x *= nv; v.y *= nv; v.z *= nv; v.w *= nv;
    float* p = xout + ((size_t)c * D + l * 4);
    asm volatile("red.global.add.v4.f32 [%0], {%1,%2,%3,%4};"
                 :: "l"(p), "f"(v.x), "f"(v.y), "f"(v.z), "f"(v.w)
                 : "memory");
}

// ---------------- batch user counts ----------------
__global__ void cnt_k(const int* __restrict__ users) {
    int t = blockIdx.x * blockDim.x + threadIdx.x;
    if (t < BATCH) atomicAdd(&g_cnt[users[t]], 1.0f);
}

// ---------------- context = sum of user embeddings (scaled later) ----------
// 16 blocks x 64 threads; block handles 64 users, thread = one dim.
__global__ void usum_k(const int* __restrict__ users, const float* __restrict__ x) {
    int d = threadIdx.x;
    float s = 0.0f;
    #pragma unroll 8
    for (int k = 0; k < 64; k++) {
        int u = users[blockIdx.x * 64 + k];
        s += x[(size_t)u * D + d];
    }
    atomicAdd(&g_usum[d], s);
}

// ---------------- softmax-weighted neighbor aggregation over edges ---------
// mx subtraction skipped: cancels exactly in acc/z and the 1e-12 clip cannot
// bind (max selected edge contributes mult*exp(0) >= 1). Logits are tiny.
__global__ void __launch_bounds__(256) softmax_k(const int* __restrict__ row,
                                                 const int* __restrict__ col,
                                                 const float* __restrict__ x) {
    __shared__ float s_us[D];
    __shared__ float s_acc[D];
    __shared__ float s_z;
    int tid = threadIdx.x;
    if (tid < D) {
        s_us[tid]  = g_usum[tid] * (1.0f / (float)BATCH);  // context, ALPHA_PREF=1
        s_acc[tid] = 0.0f;
    }
    if (tid == 0) s_z = 0.0f;
    __syncthreads();

    int stride = gridDim.x * blockDim.x;
    for (int e = blockIdx.x * blockDim.x + tid; e < EDGES; e += stride) {
        float m = g_cnt[row[e]];
        if (m > 0.0f) {                      // ~0.7% of edges
            const float4* nv = (const float4*)(x + (size_t)col[e] * D);
            float4 v[16];
            float dot = 0.0f;
            #pragma unroll
            for (int i = 0; i < 16; i++) {
                v[i] = nv[i];
                dot += v[i].x * s_us[4*i]   + v[i].y * s_us[4*i+1]
                     + v[i].z * s_us[4*i+2] + v[i].w * s_us[4*i+3];
            }
            float w = m * expf(dot);
            atomicAdd(&s_z, w);
            #pragma unroll
            for (int i = 0; i < 16; i++) {
                atomicAdd(&s_acc[4*i],   w * v[i].x);
                atomicAdd(&s_acc[4*i+1], w * v[i].y);
                atomicAdd(&s_acc[4*i+2], w * v[i].z);
                atomicAdd(&s_acc[4*i+3], w * v[i].w);
            }
        }
    }
    __syncthreads();
    if (tid < D) atomicAdd(&g_acc[tid], s_acc[tid]);
    if (tid == 0) atomicAdd(&g_z[0], s_z);
}

// ---------------- final scores: sigmoid(u.i + u.(acc/z)) -------------------
__global__ void score_k(const int* __restrict__ users, const int* __restrict__ items,
                        const float* __restrict__ x, float* __restrict__ out) {
    int w = (blockIdx.x * blockDim.x + threadIdx.x) >> 5;
    int lane = threadIdx.x & 31;
    if (w >= BATCH) return;
    int u  = users[w];
    int it = items[w] + NUM_USERS;
    float zc = fmaxf(g_z[0], 1e-12f);
    float2 ue = ((const float2*)(x + (size_t)u  * D))[lane];
    float2 ie = ((const float2*)(x + (size_t)it * D))[lane];
    float2 ac = ((const float2*)g_acc)[lane];
    float s = ue.x * ie.x + ue.y * ie.y + (ue.x * ac.x + ue.y * ac.y) / zc;
    #pragma unroll
    for (int o = 16; o; o >>= 1) s += __shfl_xor_sync(0xffffffffu, s, o);
    if (lane == 0) out[w] = 1.0f / (1.0f + expf(-s));
}

// ---------------- launcher (graph-capturable, allocation-free) -------------
extern "C" void kernel_launch(void* const* d_in, const int* in_sizes, int n_in,
                              void* d_out, int out_size) {
    const float* embed = (const float*)d_in[0];        // [150000, 64] f32
    const int*   row   = (const int*)d_in[1];          // edge_index[0]
    const int*   col   = row + EDGES;                  // edge_index[1]
    const int*   users = (const int*)d_in[2];          // [1024] i32
    const int*   items = (const int*)d_in[3];          // [1024] i32
    float*       out   = (float*)d_out;                // [1024] f32

    void *x0p, *x1p, *degp, *cntp, *usump, *accp, *zp;
    cudaGetSymbolAddress(&x0p,   g_x0);
    cudaGetSymbolAddress(&x1p,   g_x1);
    cudaGetSymbolAddress(&degp,  g_deg);
    cudaGetSymbolAddress(&cntp,  g_cnt);
    cudaGetSymbolAddress(&usump, g_usum);
    cudaGetSymbolAddress(&accp,  g_acc);
    cudaGetSymbolAddress(&zp,    g_z);
    float* x0 = (float*)x0p;
    float* x1 = (float*)x1p;

    const size_t XBYTES = (size_t)N_NODES * D * sizeof(float);
    const int EB = (EDGES + 255) / 256;               // edge-parallel blocks
    const int PB = (EDGES * 16) / 256;                // 16 threads/edge blocks

    // degree + norm (deterministic integer counts in f32)
    cudaMemsetAsync(degp, 0, N_NODES * sizeof(float));
    deg_k<<<EB, 256>>>(row);
    norm_k<<<EB, 256>>>(row, col);

    // 3 propagation layers: embed -> x0 -> x1 -> x0
    cudaMemsetAsync(x0p, 0, XBYTES);
    prop_k<<<PB, 256>>>((const float4*)embed, x0, row, col);
    cudaMemsetAsync(x1p, 0, XBYTES);
    prop_k<<<PB, 256>>>((const float4*)x0, x1, row, col);
    cudaMemsetAsync(x0p, 0, XBYTES);
    prop_k<<<PB, 256>>>((const float4*)x1, x0, row, col);

    // batch epilogue
    cudaMemsetAsync(cntp,  0, N_NODES * sizeof(float));
    cudaMemsetAsync(usump, 0, D * sizeof(float));
    cudaMemsetAsync(accp,  0, D * sizeof(float));
    cudaMemsetAsync(zp,    0, sizeof(float));
    cnt_k<<<4, 256>>>(users);
    usum_k<<<16, 64>>>(users, x0);
    softmax_k<<<1184, 256>>>(row, col, x0);
    score_k<<<BATCH * 32 / 256, 256>>>(users, items, x0, out);
}

// round 4
// speedup vs baseline: 1.4727x; 1.4727x over previous
#include <cuda_runtime.h>

#define NUM_USERS 100000
#define N_NODES   150000
#define D         64
#define EDGES     2000000
#define BATCH     1024
#define SCAN_B    1024
#define NBLK      ((N_NODES + SCAN_B - 1) / SCAN_B)   // 147

// ---------------- scratch (device globals: allocation-free) ----------------
__device__ float g_x0[(size_t)N_NODES * D];   // 38.4 MB
__device__ float g_x1[(size_t)N_NODES * D];   // 38.4 MB
__device__ int2  g_csr[EDGES];                // 16 MB  {src_row, norm bits} sorted by col
__device__ int   g_off[N_NODES + 1];
__device__ int   g_pos[N_NODES];
__device__ int   g_colcnt[N_NODES];
__device__ int   g_bsum[NBLK];
__device__ float g_deg[N_NODES];
__device__ float g_cnt[N_NODES];
__device__ float g_usum[D];
__device__ float g_acc[D];
__device__ float g_z[1];

// ---------------- fused histograms: row degree (float) + col count (int) ---
__global__ void hist_k(const int* __restrict__ row, const int* __restrict__ col) {
    int t = blockIdx.x * blockDim.x + threadIdx.x;
    if (t < EDGES) {
        atomicAdd(&g_deg[row[t]], 1.0f);
        atomicAdd(&g_colcnt[col[t]], 1);
    }
}

// ---------------- 3-kernel exclusive prefix scan over colcnt ---------------
__global__ void scan1_k() {
    __shared__ int sh[SCAN_B];
    int i = blockIdx.x * SCAN_B + threadIdx.x;
    int v = (i < N_NODES) ? g_colcnt[i] : 0;
    sh[threadIdx.x] = v;
    __syncthreads();
    for (int d = 1; d < SCAN_B; d <<= 1) {
        int t = (threadIdx.x >= d) ? sh[threadIdx.x - d] : 0;
        __syncthreads();
        sh[threadIdx.x] += t;
        __syncthreads();
    }
    if (i < N_NODES) g_off[i] = sh[threadIdx.x] - v;          // exclusive within block
    if (threadIdx.x == SCAN_B - 1) g_bsum[blockIdx.x] = sh[threadIdx.x];
}
__global__ void scan2_k() {          // tiny: 147 elements, 1 thread
    int acc = 0;
    for (int i = 0; i < NBLK; i++) { int t = g_bsum[i]; g_bsum[i] = acc; acc += t; }
    g_off[N_NODES] = EDGES;
}
__global__ void scan3_k() {
    int i = blockIdx.x * SCAN_B + threadIdx.x;
    if (i < N_NODES) {
        int v = g_off[i] + g_bsum[blockIdx.x];
        g_off[i] = v;
        g_pos[i] = v;                // scatter cursors start at segment base
    }
}

// ---------------- counting-sort scatter: edges sorted by col ---------------
__global__ void scatter_k(const int* __restrict__ row, const int* __restrict__ col) {
    int e = blockIdx.x * blockDim.x + threadIdx.x;
    if (e >= EDGES) return;
    int r = row[e], c = col[e];
    float nv = rsqrtf(fmaxf(g_deg[r], 1.0f)) * rsqrtf(fmaxf(g_deg[c], 1.0f));
    int p = atomicAdd(&g_pos[c], 1);
    g_csr[p] = make_int2(r, __float_as_int(nv));
}

// ---------------- one propagation layer (CSR gather, no atomics) -----------
// 16 lanes per node, float4 per lane; 2 nodes per warp.
__global__ void __launch_bounds__(256) prop_csr_k(const float4* __restrict__ xin,
                                                  float4* __restrict__ xout) {
    unsigned t = blockIdx.x * blockDim.x + threadIdx.x;
    unsigned node = t >> 4;
    unsigned lane = t & 15;
    if (node >= N_NODES) return;
    int s = g_off[node];
    int e = g_off[node + 1];
    float4 acc = make_float4(0.f, 0.f, 0.f, 0.f);
    int k = s;
    for (; k + 1 < e; k += 2) {                 // 2-way unroll for gather MLP
        int2 e0 = g_csr[k];
        int2 e1 = g_csr[k + 1];
        float4 v0 = xin[(size_t)e0.x * 16 + lane];
        float4 v1 = xin[(size_t)e1.x * 16 + lane];
        float n0 = __int_as_float(e0.y);
        float n1 = __int_as_float(e1.y);
        acc.x += n0 * v0.x + n1 * v1.x;
        acc.y += n0 * v0.y + n1 * v1.y;
        acc.z += n0 * v0.z + n1 * v1.z;
        acc.w += n0 * v0.w + n1 * v1.w;
    }
    if (k < e) {
        int2 e0 = g_csr[k];
        float4 v0 = xin[(size_t)e0.x * 16 + lane];
        float n0 = __int_as_float(e0.y);
        acc.x += n0 * v0.x; acc.y += n0 * v0.y;
        acc.z += n0 * v0.z; acc.w += n0 * v0.w;
    }
    xout[(size_t)node * 16 + lane] = acc;
}

// ---------------- batch user counts ----------------
__global__ void cnt_k(const int* __restrict__ users) {
    int t = blockIdx.x * blockDim.x + threadIdx.x;
    if (t < BATCH) atomicAdd(&g_cnt[users[t]], 1.0f);
}

// ---------------- context = sum of user embeddings -------------------------
__global__ void usum_k(const int* __restrict__ users, const float* __restrict__ x) {
    int d = threadIdx.x;
    float s = 0.0f;
    #pragma unroll 8
    for (int k = 0; k < 64; k++) {
        int u = users[blockIdx.x * 64 + k];
        s += x[(size_t)u * D + d];
    }
    atomicAdd(&g_usum[d], s);
}

// ---------------- softmax-weighted neighbor aggregation over edges ---------
// mx subtraction skipped: cancels exactly in acc/z; clip(1e-12) cannot bind.
__global__ void __launch_bounds__(256) softmax_k(const int* __restrict__ row,
                                                 const int* __restrict__ col,
                                                 const float* __restrict__ x) {
    __shared__ float s_us[D];
    __shared__ float s_acc[D];
    __shared__ float s_z;
    int tid = threadIdx.x;
    if (tid < D) {
        s_us[tid]  = g_usum[tid] * (1.0f / (float)BATCH);  // context, ALPHA_PREF=1
        s_acc[tid] = 0.0f;
    }
    if (tid == 0) s_z = 0.0f;
    __syncthreads();

    int stride = gridDim.x * blockDim.x;
    for (int e = blockIdx.x * blockDim.x + tid; e < EDGES; e += stride) {
        float m = g_cnt[row[e]];
        if (m > 0.0f) {                      // ~0.7% of edges
            const float4* nv = (const float4*)(x + (size_t)col[e] * D);
            float4 v[16];
            float dot = 0.0f;
            #pragma unroll
            for (int i = 0; i < 16; i++) {
                v[i] = nv[i];
                dot += v[i].x * s_us[4*i]   + v[i].y * s_us[4*i+1]
                     + v[i].z * s_us[4*i+2] + v[i].w * s_us[4*i+3];
            }
            float w = m * expf(dot);
            atomicAdd(&s_z, w);
            #pragma unroll
            for (int i = 0; i < 16; i++) {
                atomicAdd(&s_acc[4*i],   w * v[i].x);
                atomicAdd(&s_acc[4*i+1], w * v[i].y);
                atomicAdd(&s_acc[4*i+2], w * v[i].z);
                atomicAdd(&s_acc[4*i+3], w * v[i].w);
            }
        }
    }
    __syncthreads();
    if (tid < D) atomicAdd(&g_acc[tid], s_acc[tid]);
    if (tid == 0) atomicAdd(&g_z[0], s_z);
}

// ---------------- final scores: sigmoid(u.i + u.(acc/z)) -------------------
__global__ void score_k(const int* __restrict__ users, const int* __restrict__ items,
                        const float* __restrict__ x, float* __restrict__ out) {
    int w = (blockIdx.x * blockDim.x + threadIdx.x) >> 5;
    int lane = threadIdx.x & 31;
    if (w >= BATCH) return;
    int u  = users[w];
    int it = items[w] + NUM_USERS;
    float zc = fmaxf(g_z[0], 1e-12f);
    float2 ue = ((const float2*)(x + (size_t)u  * D))[lane];
    float2 ie = ((const float2*)(x + (size_t)it * D))[lane];
    float2 ac = ((const float2*)g_acc)[lane];
    float s = ue.x * ie.x + ue.y * ie.y + (ue.x * ac.x + ue.y * ac.y) / zc;
    #pragma unroll
    for (int o = 16; o; o >>= 1) s += __shfl_xor_sync(0xffffffffu, s, o);
    if (lane == 0) out[w] = 1.0f / (1.0f + expf(-s));
}

// ---------------- launcher (graph-capturable, allocation-free) -------------
extern "C" void kernel_launch(void* const* d_in, const int* in_sizes, int n_in,
                              void* d_out, int out_size) {
    const float* embed = (const float*)d_in[0];        // [150000, 64] f32
    const int*   row   = (const int*)d_in[1];          // edge_index[0]
    const int*   col   = row + EDGES;                  // edge_index[1]
    const int*   users = (const int*)d_in[2];          // [1024] i32
    const int*   items = (const int*)d_in[3];          // [1024] i32
    float*       out   = (float*)d_out;                // [1024] f32

    void *x0p, *x1p, *degp, *ccp, *cntp, *usump, *accp, *zp;
    cudaGetSymbolAddress(&x0p,   g_x0);
    cudaGetSymbolAddress(&x1p,   g_x1);
    cudaGetSymbolAddress(&degp,  g_deg);
    cudaGetSymbolAddress(&ccp,   g_colcnt);
    cudaGetSymbolAddress(&cntp,  g_cnt);
    cudaGetSymbolAddress(&usump, g_usum);
    cudaGetSymbolAddress(&accp,  g_acc);
    cudaGetSymbolAddress(&zp,    g_z);
    float* x0 = (float*)x0p;
    float* x1 = (float*)x1p;

    const int EB = (EDGES + 255) / 256;                 // edge-parallel blocks
    const int PB = (N_NODES * 16 + 255) / 256;          // 16 threads/node blocks

    // zero the small scratch
    cudaMemsetAsync(degp,  0, N_NODES * sizeof(float));
    cudaMemsetAsync(ccp,   0, N_NODES * sizeof(int));
    cudaMemsetAsync(cntp,  0, N_NODES * sizeof(float));
    cudaMemsetAsync(usump, 0, D * sizeof(float));
    cudaMemsetAsync(accp,  0, D * sizeof(float));
    cudaMemsetAsync(zp,    0, sizeof(float));

    // CSR build: histograms -> exclusive scan -> counting-sort scatter
    hist_k<<<EB, 256>>>(row, col);
    scan1_k<<<NBLK, SCAN_B>>>();
    scan2_k<<<1, 1>>>();
    scan3_k<<<NBLK, SCAN_B>>>();
    scatter_k<<<EB, 256>>>(row, col);

    // 3 propagation layers (gather, no atomics): embed -> x0 -> x1 -> x0
    prop_csr_k<<<PB, 256>>>((const float4*)embed, (float4*)x0);
    prop_csr_k<<<PB, 256>>>((const float4*)x0,    (float4*)x1);
    prop_csr_k<<<PB, 256>>>((const float4*)x1,    (float4*)x0);

    // batch epilogue
    cnt_k<<<4, 256>>>(users);
    usum_k<<<16, 64>>>(users, x0);
    softmax_k<<<1184, 256>>>(row, col, x0);
    score_k<<<BATCH * 32 / 256, 256>>>(users, items, x0, out);
}